// round 7
// baseline (speedup 1.0000x reference)
#include <cuda_runtime.h>
#include <math.h>

// ContLoss: T=512, B=64, E=1024, N=128
#define TT     512
#define BZ     64
#define EE     1024
#define NNEG   128
#define EPSV   1e-8f
#define INV_TEMP 10.0f   // 1/TEMP, TEMP=0.1

#define SLOTS  5     // smem ring slots
#define RPS    2     // rows per stage
#define NST    (NNEG / RPS)   // 64 stages

// scratch (zero-initialized __device__ globals)
__device__ float        g_partial[TT];
__device__ unsigned int g_count;

__device__ __forceinline__ void cp_async16(unsigned smem_dst, const void* gsrc) {
    asm volatile("cp.async.cg.shared.global [%0], [%1], 16;" :: "r"(smem_dst), "l"(gsrc));
}
__device__ __forceinline__ void cp_commit() {
    asm volatile("cp.async.commit_group;");
}
template <int N>
__device__ __forceinline__ void cp_wait() {
    asm volatile("cp.async.wait_group %0;" :: "n"(N));
}

// One CTA per t. 256 threads; thread tid owns float4 column tid.
// cp.async ring: each thread streams its own 16B chunk of each negative row
// through smem — per-thread pipeline, no barriers, 4 groups (32KB) in flight.
// Tail iterations commit EMPTY groups so wait_group<4> accounting stays exact.
__global__ __launch_bounds__(256) void contloss_fused(
    const int*   __restrict__ index,
    const float* __restrict__ z1,
    const float* __restrict__ z2,
    const int*   __restrict__ neg_s,
    const int*   __restrict__ neg_w,
    float*       __restrict__ out)
{
    const int t   = blockIdx.x;
    const int tid = threadIdx.x;

    __shared__ int    sh_off[NNEG];
    __shared__ float4 buf[SLOTS][RPS][256];   // 40 KB ring

    if (tid < NNEG) {
        const int j = t * NNEG + tid;
        sh_off[tid] = (neg_s[j] * BZ + neg_w[j]) * (EE / 4);
    }
    __syncthreads();

    const float4* __restrict__ z1v = (const float4*)z1;
    const unsigned buf_base =
        (unsigned)__cvta_generic_to_shared(&buf[0][0][0]) + tid * 16u;

    // issue one stage (RPS rows) into its ring slot; ALWAYS commit a group
    // (empty for st >= NST) so group counting is uniform through the tail.
    auto issue = [&](int st) {
        if (st < NST) {
            const int slot = st % SLOTS;
            #pragma unroll
            for (int r = 0; r < RPS; ++r) {
                const unsigned dst = buf_base + (unsigned)((slot * RPS + r) * 4096);
                cp_async16(dst, (const void*)(z1v + sh_off[st * RPS + r] + tid));
            }
        }
        cp_commit();
    };

    // prologue: 4 stages in flight
    issue(0); issue(1); issue(2); issue(3);

    float s0 = 0.f, s1 = 0.f, s2 = 0.f, s3 = 0.f;
    float q0 = 0.f, q1 = 0.f, q2 = 0.f, q3 = 0.f;

    for (int it = 0; it < NST; ++it) {
        issue(it + 4);         // empty commit in the tail
        cp_wait<4>();          // oldest data group (stage it) complete
        const int slot = it % SLOTS;
        #pragma unroll
        for (int r = 0; r < RPS; ++r) {
            const float4 v = buf[slot][r][tid];
            s0 += v.x; s1 += v.y; s2 += v.z; s3 += v.w;
            q0 = fmaf(v.x, v.x, q0); q1 = fmaf(v.y, v.y, q1);
            q2 = fmaf(v.z, v.z, q2); q3 = fmaf(v.w, v.w, q3);
        }
    }
    cp_wait<0>();

    // anchor (orig) and positive (adv) rows
    const int bidx  = __ldg(index + t);
    const int arow4 = (t * BZ + bidx) * (EE / 4);
    const float4 vo = __ldg(z1v + arow4 + tid);
    const float4 va = __ldg((const float4*)z2 + arow4 + tid);

    const float sqrtN = sqrtf((float)NNEG);

    float den = 0.f;
    {
        float o, sm, qq;
        o = vo.x; sm = s0; qq = q0;
        den += expf((o * sm) / (fmaxf(sqrtf(qq), EPSV) * fmaxf(sqrtN * fabsf(o), EPSV)) * INV_TEMP);
        o = vo.y; sm = s1; qq = q1;
        den += expf((o * sm) / (fmaxf(sqrtf(qq), EPSV) * fmaxf(sqrtN * fabsf(o), EPSV)) * INV_TEMP);
        o = vo.z; sm = s2; qq = q2;
        den += expf((o * sm) / (fmaxf(sqrtf(qq), EPSV) * fmaxf(sqrtN * fabsf(o), EPSV)) * INV_TEMP);
        o = vo.w; sm = s3; qq = q3;
        den += expf((o * sm) / (fmaxf(sqrtf(qq), EPSV) * fmaxf(sqrtN * fabsf(o), EPSV)) * INV_TEMP);
    }
    float dotp = vo.x * va.x + vo.y * va.y + vo.z * va.z + vo.w * va.w;
    float na2  = vo.x * vo.x + vo.y * vo.y + vo.z * vo.z + vo.w * vo.w;
    float nb2  = va.x * va.x + va.y * va.y + va.z * va.z + va.w * va.w;

    // deterministic block reduction
    const int lane = tid & 31;
    const int warp = tid >> 5;
    #pragma unroll
    for (int off = 16; off > 0; off >>= 1) {
        den  += __shfl_down_sync(0xffffffffu, den,  off);
        dotp += __shfl_down_sync(0xffffffffu, dotp, off);
        na2  += __shfl_down_sync(0xffffffffu, na2,  off);
        nb2  += __shfl_down_sync(0xffffffffu, nb2,  off);
    }
    __shared__ float r_den[8], r_dot[8], r_na[8], r_nb[8];
    __shared__ bool  sh_last;
    if (lane == 0) {
        r_den[warp] = den; r_dot[warp] = dotp; r_na[warp] = na2; r_nb[warp] = nb2;
    }
    __syncthreads();
    if (tid == 0) {
        float D = 0.f, P = 0.f, A = 0.f, Bv = 0.f;
        #pragma unroll
        for (int w = 0; w < 8; ++w) { D += r_den[w]; P += r_dot[w]; A += r_na[w]; Bv += r_nb[w]; }
        const float pos_cos = P / (fmaxf(sqrtf(A), EPSV) * fmaxf(sqrtf(Bv), EPSV));
        g_partial[t] = logf(D) - pos_cos * INV_TEMP;
        __threadfence();
        const unsigned int done = atomicAdd(&g_count, 1u);
        sh_last = (done == (unsigned int)(gridDim.x - 1));
    }
    __syncthreads();

    // global-last CTA: deterministic tree over the 512 per-t losses
    if (sh_last) {
        __shared__ float sh[256];
        sh[tid] = g_partial[tid] + g_partial[tid + 256];
        __syncthreads();
        #pragma unroll
        for (int s = 128; s > 0; s >>= 1) {
            if (tid < s) sh[tid] += sh[tid + s];
            __syncthreads();
        }
        if (tid == 0) {
            out[0]  = sh[0];
            g_count = 0u;   // reset for next graph replay
        }
    }
}

extern "C" void kernel_launch(void* const* d_in, const int* in_sizes, int n_in,
                              void* d_out, int out_size)
{
    const int*   index = (const int*)  d_in[0];
    const float* z1    = (const float*)d_in[1];
    const float* z2    = (const float*)d_in[2];
    const int*   ns    = (const int*)  d_in[3];
    const int*   nw    = (const int*)  d_in[4];

    contloss_fused<<<TT, 256>>>(index, z1, z2, ns, nw, (float*)d_out);
}

// round 8
// speedup vs baseline: 1.2279x; 1.2279x over previous
#include <cuda_runtime.h>
#include <math.h>

// ContLoss: T=512, B=64, E=1024, N=128
#define TT     512
#define BZ     64
#define EE     1024
#define NNEG   128
#define EPSV   1e-8f
#define INV_TEMP 10.0f   // 1/TEMP, TEMP=0.1

// scratch (zero-initialized __device__ globals)
__device__ float        g_partial[TT];
__device__ unsigned int g_count;

// asm-forced vector load: ordering vs other asm volatile is guaranteed,
// so batches of these CANNOT be sunk by ptxas.
__device__ __forceinline__ float4 ldg128(const float4* p) {
    float4 v;
    asm volatile("ld.global.nc.v4.f32 {%0,%1,%2,%3}, [%4];"
                 : "=f"(v.x), "=f"(v.y), "=f"(v.z), "=f"(v.w)
                 : "l"(p));
    return v;
}

// One CTA per t. 256 threads; thread tid owns float4 column tid.
// Hot loop: 8 asm-batched LDG.128 in flight per thread (true MLP=8).
__global__ __launch_bounds__(256, 4) void contloss_fused(
    const int*   __restrict__ index,
    const float* __restrict__ z1,
    const float* __restrict__ z2,
    const int*   __restrict__ neg_s,
    const int*   __restrict__ neg_w,
    float*       __restrict__ out)
{
    const int t   = blockIdx.x;
    const int tid = threadIdx.x;

    __shared__ int sh_off[NNEG];
    if (tid < NNEG) {
        const int j = t * NNEG + tid;
        sh_off[tid] = (neg_s[j] * BZ + neg_w[j]) * (EE / 4);
    }
    __syncthreads();

    const float4* __restrict__ z1v = (const float4*)z1;

    float s0 = 0.f, s1 = 0.f, s2 = 0.f, s3 = 0.f;
    float q0 = 0.f, q1 = 0.f, q2 = 0.f, q3 = 0.f;

    for (int n = 0; n < NNEG; n += 8) {
        // 8 guaranteed back-to-back LDG.128 (asm volatile order is preserved)
        const float4 v0 = ldg128(z1v + sh_off[n + 0] + tid);
        const float4 v1 = ldg128(z1v + sh_off[n + 1] + tid);
        const float4 v2 = ldg128(z1v + sh_off[n + 2] + tid);
        const float4 v3 = ldg128(z1v + sh_off[n + 3] + tid);
        const float4 v4 = ldg128(z1v + sh_off[n + 4] + tid);
        const float4 v5 = ldg128(z1v + sh_off[n + 5] + tid);
        const float4 v6 = ldg128(z1v + sh_off[n + 6] + tid);
        const float4 v7 = ldg128(z1v + sh_off[n + 7] + tid);

        s0 += v0.x; s1 += v0.y; s2 += v0.z; s3 += v0.w;
        q0 = fmaf(v0.x, v0.x, q0); q1 = fmaf(v0.y, v0.y, q1);
        q2 = fmaf(v0.z, v0.z, q2); q3 = fmaf(v0.w, v0.w, q3);

        s0 += v1.x; s1 += v1.y; s2 += v1.z; s3 += v1.w;
        q0 = fmaf(v1.x, v1.x, q0); q1 = fmaf(v1.y, v1.y, q1);
        q2 = fmaf(v1.z, v1.z, q2); q3 = fmaf(v1.w, v1.w, q3);

        s0 += v2.x; s1 += v2.y; s2 += v2.z; s3 += v2.w;
        q0 = fmaf(v2.x, v2.x, q0); q1 = fmaf(v2.y, v2.y, q1);
        q2 = fmaf(v2.z, v2.z, q2); q3 = fmaf(v2.w, v2.w, q3);

        s0 += v3.x; s1 += v3.y; s2 += v3.z; s3 += v3.w;
        q0 = fmaf(v3.x, v3.x, q0); q1 = fmaf(v3.y, v3.y, q1);
        q2 = fmaf(v3.z, v3.z, q2); q3 = fmaf(v3.w, v3.w, q3);

        s0 += v4.x; s1 += v4.y; s2 += v4.z; s3 += v4.w;
        q0 = fmaf(v4.x, v4.x, q0); q1 = fmaf(v4.y, v4.y, q1);
        q2 = fmaf(v4.z, v4.z, q2); q3 = fmaf(v4.w, v4.w, q3);

        s0 += v5.x; s1 += v5.y; s2 += v5.z; s3 += v5.w;
        q0 = fmaf(v5.x, v5.x, q0); q1 = fmaf(v5.y, v5.y, q1);
        q2 = fmaf(v5.z, v5.z, q2); q3 = fmaf(v5.w, v5.w, q3);

        s0 += v6.x; s1 += v6.y; s2 += v6.z; s3 += v6.w;
        q0 = fmaf(v6.x, v6.x, q0); q1 = fmaf(v6.y, v6.y, q1);
        q2 = fmaf(v6.z, v6.z, q2); q3 = fmaf(v6.w, v6.w, q3);

        s0 += v7.x; s1 += v7.y; s2 += v7.z; s3 += v7.w;
        q0 = fmaf(v7.x, v7.x, q0); q1 = fmaf(v7.y, v7.y, q1);
        q2 = fmaf(v7.z, v7.z, q2); q3 = fmaf(v7.w, v7.w, q3);
    }

    // anchor (orig) and positive (adv) rows
    const int bidx  = __ldg(index + t);
    const int arow4 = (t * BZ + bidx) * (EE / 4);
    const float4 vo = __ldg(z1v + arow4 + tid);
    const float4 va = __ldg((const float4*)z2 + arow4 + tid);

    const float sqrtN = sqrtf((float)NNEG);

    float den = 0.f;
    {
        float o, sm, qq;
        o = vo.x; sm = s0; qq = q0;
        den += expf((o * sm) / (fmaxf(sqrtf(qq), EPSV) * fmaxf(sqrtN * fabsf(o), EPSV)) * INV_TEMP);
        o = vo.y; sm = s1; qq = q1;
        den += expf((o * sm) / (fmaxf(sqrtf(qq), EPSV) * fmaxf(sqrtN * fabsf(o), EPSV)) * INV_TEMP);
        o = vo.z; sm = s2; qq = q2;
        den += expf((o * sm) / (fmaxf(sqrtf(qq), EPSV) * fmaxf(sqrtN * fabsf(o), EPSV)) * INV_TEMP);
        o = vo.w; sm = s3; qq = q3;
        den += expf((o * sm) / (fmaxf(sqrtf(qq), EPSV) * fmaxf(sqrtN * fabsf(o), EPSV)) * INV_TEMP);
    }
    float dotp = vo.x * va.x + vo.y * va.y + vo.z * va.z + vo.w * va.w;
    float na2  = vo.x * vo.x + vo.y * vo.y + vo.z * vo.z + vo.w * vo.w;
    float nb2  = va.x * va.x + va.y * va.y + va.z * va.z + va.w * va.w;

    // deterministic block reduction
    const int lane = tid & 31;
    const int warp = tid >> 5;
    #pragma unroll
    for (int off = 16; off > 0; off >>= 1) {
        den  += __shfl_down_sync(0xffffffffu, den,  off);
        dotp += __shfl_down_sync(0xffffffffu, dotp, off);
        na2  += __shfl_down_sync(0xffffffffu, na2,  off);
        nb2  += __shfl_down_sync(0xffffffffu, nb2,  off);
    }
    __shared__ float r_den[8], r_dot[8], r_na[8], r_nb[8];
    __shared__ bool  sh_last;
    if (lane == 0) {
        r_den[warp] = den; r_dot[warp] = dotp; r_na[warp] = na2; r_nb[warp] = nb2;
    }
    __syncthreads();
    if (tid == 0) {
        float D = 0.f, P = 0.f, A = 0.f, Bv = 0.f;
        #pragma unroll
        for (int w = 0; w < 8; ++w) { D += r_den[w]; P += r_dot[w]; A += r_na[w]; Bv += r_nb[w]; }
        const float pos_cos = P / (fmaxf(sqrtf(A), EPSV) * fmaxf(sqrtf(Bv), EPSV));
        g_partial[t] = logf(D) - pos_cos * INV_TEMP;
        __threadfence();
        const unsigned int done = atomicAdd(&g_count, 1u);
        sh_last = (done == (unsigned int)(gridDim.x - 1));
    }
    __syncthreads();

    // global-last CTA: deterministic tree over the 512 per-t losses
    if (sh_last) {
        __shared__ float sh[256];
        sh[tid] = g_partial[tid] + g_partial[tid + 256];
        __syncthreads();
        #pragma unroll
        for (int s = 128; s > 0; s >>= 1) {
            if (tid < s) sh[tid] += sh[tid + s];
            __syncthreads();
        }
        if (tid == 0) {
            out[0]  = sh[0];
            g_count = 0u;   // reset for next graph replay
        }
    }
}

extern "C" void kernel_launch(void* const* d_in, const int* in_sizes, int n_in,
                              void* d_out, int out_size)
{
    const int*   index = (const int*)  d_in[0];
    const float* z1    = (const float*)d_in[1];
    const float* z2    = (const float*)d_in[2];
    const int*   ns    = (const int*)  d_in[3];
    const int*   nw    = (const int*)  d_in[4];

    contloss_fused<<<TT, 256>>>(index, z1, z2, ns, nw, (float*)d_out);
}